// round 17
// baseline (speedup 1.0000x reference)
#include <cuda_runtime.h>
#include <cuda_fp16.h>
#include <cstdint>

#define BATCH 4096
#define TDIM  1024
#define GATES 512
#define CHUNK 128
#define NCH   8

// ---------- device scratch --------------------------------------------------
__device__ float  g_pre[(size_t)BATCH * CHUNK * GATES];  // 1 GB staging (per chunk)
__device__ __half g_Bih[GATES * 128];                    // W_ih reordered [n][k] fp16
__device__ __half g_Bhh[GATES * 128];                    // W_hh reordered [n][k] fp16
__device__ float  g_bias[GATES];                         // b_ih+b_hh, reordered
__device__ float  g_h[BATCH * 128];
__device__ float  g_c[BATCH * 128];

// ---------- helpers ---------------------------------------------------------
__device__ __forceinline__ uint32_t smem_u32(const void* p) {
    uint32_t a;
    asm("{ .reg .u64 t; cvta.to.shared.u64 t, %1; cvt.u32.u64 %0, t; }" : "=r"(a) : "l"(p));
    return a;
}
__device__ __forceinline__ void ldm_x4(uint32_t* r, uint32_t addr) {
    asm volatile("ldmatrix.sync.aligned.m8n8.x4.shared.b16 {%0,%1,%2,%3},[%4];"
                 : "=r"(r[0]), "=r"(r[1]), "=r"(r[2]), "=r"(r[3]) : "r"(addr));
}
__device__ __forceinline__ void mma16816(float& d0, float& d1, float& d2, float& d3,
                                         uint32_t a0, uint32_t a1, uint32_t a2, uint32_t a3,
                                         uint32_t b0, uint32_t b1) {
    asm volatile("mma.sync.aligned.m16n8k16.row.col.f32.f16.f16.f32 "
                 "{%0,%1,%2,%3},{%4,%5,%6,%7},{%8,%9},{%0,%1,%2,%3};"
                 : "+f"(d0), "+f"(d1), "+f"(d2), "+f"(d3)
                 : "r"(a0), "r"(a1), "r"(a2), "r"(a3), "r"(b0), "r"(b1));
}
__device__ __forceinline__ float sigf(float x) {
    return __fdividef(1.f, 1.f + __expf(-x));
}
__device__ __forceinline__ float tanhfast(float x) {
    return 1.f - __fdividef(2.f, __expf(2.f * x) + 1.f);
}
// split x into hi (fp16) + lo (fp16 residual)
__device__ __forceinline__ void split2(float x, __half& hi, __half& lo) {
    hi = __float2half(x);
    lo = __float2half(x - __half2float(hi));
}

// row padding: 128 halves -> 272 bytes (row skew = 4 banks; conflict-free ldmatrix)
#define ROWB 272

// ---------- prep: reorder weights to [n][k], n = 4*cell + gate(i,f,g,o) -----
__global__ void k_prep(const float* __restrict__ Wih, const float* __restrict__ Whh,
                       const float* __restrict__ bih, const float* __restrict__ bhh) {
    int i = blockIdx.x * 256 + threadIdx.x;     // 512*128
    if (i >= GATES * 128) return;
    int n = i >> 7, k = i & 127;
    int go = (n & 3) * 128 + (n >> 2);          // original gate row
    g_Bih[n * 128 + k] = __float2half(Wih[go * 128 + k]);
    g_Bhh[n * 128 + k] = __float2half(Whh[go * 128 + k]);
    if (k == 0) g_bias[n] = bih[go] + bhh[go];
}

__global__ void k_zero() {
    int i = blockIdx.x * 256 + threadIdx.x;
    if (i < BATCH * 128) { g_h[i] = 0.f; g_c[i] = 0.f; }
}

// ---------- phase 1 (HMMA): pre = relu(x@We^T+be) @ Wih^T + bias ------------
#define P1_B    0                    // 512 rows x 272B = 139264
#define P1_EH   139264               // 128 x 272B = 34816
#define P1_EL   174080               // 128 x 272B = 34816
#define P1_BIAS 208896               // 512 f32
#define P1_WE   210944               // 256 f32
#define P1_BE   211968               // 128 f32
#define P1_X    212480               // 256 f32
#define SMEM_P1 213504

__global__ __launch_bounds__(256, 1)
void k_pre_tc(const float* __restrict__ xin, const float* __restrict__ We,
              const float* __restrict__ be, int chunk) {
    extern __shared__ char sm[];
    uint32_t smb = smem_u32(sm);
    float* sBias = (float*)(sm + P1_BIAS);
    float* sWe   = (float*)(sm + P1_WE);
    float* sbe   = (float*)(sm + P1_BE);
    float* sX    = (float*)(sm + P1_X);
    int tid = threadIdx.x;
    int w = tid >> 5, lane = tid & 31;
    int tloc = blockIdx.x;
    int tg = chunk * CHUNK + tloc;

    for (int idx = tid; idx < 8192; idx += 256) {
        int n = idx >> 4, kq = idx & 15;
        *(uint4*)(sm + P1_B + n * ROWB + kq * 16) = ((const uint4*)g_Bih)[idx];
    }
    for (int i = tid; i < 512; i += 256) sBias[i] = g_bias[i];
    if (tid < 256) sWe[tid] = We[tid];
    if (tid < 128) sbe[tid] = be[tid];

    int c2 = 2 * (lane & 3), r4 = lane >> 2;
    int lr = lane & 15, lh = lane >> 4;

    for (int it = 0; it < 8; it++) {
        int b0 = blockIdx.y * 1024 + it * 128;
        __syncthreads();
        if (tid < 128) {
            float2 v = ((const float2*)xin)[(size_t)(b0 + tid) * TDIM + tg];
            sX[2 * tid] = v.x; sX[2 * tid + 1] = v.y;
        }
        __syncthreads();
        for (int j = 0; j < 32; j++) {
            int p = j * 256 + tid;
            int r = p >> 6, k2 = p & 63;
            float x0 = sX[2 * r], x1 = sX[2 * r + 1];
            int k = 2 * k2;
            float e0 = fmaxf(fmaf(sWe[2 * k],     x0, fmaf(sWe[2 * k + 1], x1, sbe[k])),     0.f);
            float e1 = fmaxf(fmaf(sWe[2 * k + 2], x0, fmaf(sWe[2 * k + 3], x1, sbe[k + 1])), 0.f);
            __half h0, l0, h1, l1;
            split2(e0, h0, l0); split2(e1, h1, l1);
            *(__half2*)(sm + P1_EH + r * ROWB + k2 * 4) = __halves2half2(h0, h1);
            *(__half2*)(sm + P1_EL + r * ROWB + k2 * 4) = __halves2half2(l0, l1);
        }
        __syncthreads();

        uint32_t ah[8][4], al[8][4];
        uint32_t ahb = smb + P1_EH + (16 * w + lr) * ROWB + lh * 16;
        uint32_t alb = smb + P1_EL + (16 * w + lr) * ROWB + lh * 16;
        #pragma unroll
        for (int ks = 0; ks < 8; ks++) { ldm_x4(ah[ks], ahb + ks * 32); ldm_x4(al[ks], alb + ks * 32); }

        size_t grow = (size_t)tloc * 4096 + b0 + 16 * w + r4;
        // groups of 4 ntiles, kp-outer: 4 independent acc chains per kp
        #pragma unroll 1
        for (int g = 0; g < 16; g++) {
            float acc[4][4];
            #pragma unroll
            for (int j = 0; j < 4; j++) {
                float2 bv = *(const float2*)(sBias + (g * 4 + j) * 8 + c2);
                acc[j][0] = bv.x; acc[j][1] = bv.y; acc[j][2] = bv.x; acc[j][3] = bv.y;
            }
            #pragma unroll
            for (int kp = 0; kp < 4; kp++) {
                #pragma unroll
                for (int j = 0; j < 4; j++) {
                    int nt = g * 4 + j;
                    uint32_t bf[4];
                    ldm_x4(bf, smb + P1_B + (nt * 8 + (lane & 7)) * ROWB + (lane >> 3) * 16 + kp * 64);
                    mma16816(acc[j][0], acc[j][1], acc[j][2], acc[j][3],
                             ah[2*kp][0], ah[2*kp][1], ah[2*kp][2], ah[2*kp][3], bf[0], bf[1]);
                    mma16816(acc[j][0], acc[j][1], acc[j][2], acc[j][3],
                             ah[2*kp+1][0], ah[2*kp+1][1], ah[2*kp+1][2], ah[2*kp+1][3], bf[2], bf[3]);
                    mma16816(acc[j][0], acc[j][1], acc[j][2], acc[j][3],
                             al[2*kp][0], al[2*kp][1], al[2*kp][2], al[2*kp][3], bf[0], bf[1]);
                    mma16816(acc[j][0], acc[j][1], acc[j][2], acc[j][3],
                             al[2*kp+1][0], al[2*kp+1][1], al[2*kp+1][2], al[2*kp+1][3], bf[2], bf[3]);
                }
            }
            #pragma unroll
            for (int j = 0; j < 4; j++) {
                int nt = g * 4 + j;
                *(float2*)(g_pre + grow * GATES + nt * 8 + c2)       = make_float2(acc[j][0], acc[j][1]);
                *(float2*)(g_pre + (grow + 8) * GATES + nt * 8 + c2) = make_float2(acc[j][2], acc[j][3]);
            }
        }
    }
}

// ---------- phase 2 (HMMA recurrence): 1 CTA = 32 batch rows, 512 threads ---
// kp-outer GEMM (8 independent acc chains), in-register activation via
// shfl.bfly pair exchange, double-buffered H -> one barrier per step,
// y-epilogue spread over lanes 0-9 of every warp.
#define P2_B   0                     // W_hh 512 x 272B = 139264
#define P2_H   139264                // 2 bufs x (HH 8704 + HL 8704) = 34816
#define HBUF   17408
#define P2_WO  174080                // 640 f32
#define P2_BO  176640                // 5 f32
#define SMEM_P2 176672

__global__ __launch_bounds__(512, 1)
void k_recur(const float* __restrict__ Wo, const float* __restrict__ bo,
             float* __restrict__ out, int chunk) {
    extern __shared__ char sm[];
    uint32_t smb = smem_u32(sm);
    float* sWo = (float*)(sm + P2_WO);
    float* sbo = (float*)(sm + P2_BO);
    int tid = threadIdx.x;
    int w = tid >> 5, lane = tid & 31;
    int mt = w >> 3, wn = w & 7;
    int b0 = blockIdx.x * 32;

    // W_hh [n][k] fp16 into padded rows
    for (int idx = tid; idx < 8192; idx += 512) {
        int n = idx >> 4, kq = idx & 15;
        *(uint4*)(sm + P2_B + n * ROWB + kq * 16) = ((const uint4*)g_Bhh)[idx];
    }
    // initial h -> buffer 1 (read buffer of step 0)
    for (int i = tid; i < 4096; i += 512) {
        int r = i >> 7, k = i & 127;
        __half hi, lo;
        split2(g_h[(b0 + r) * 128 + k], hi, lo);
        *(__half*)(sm + P2_H + HBUF + r * ROWB + k * 2) = hi;
        *(__half*)(sm + P2_H + HBUF + 8704 + r * ROWB + k * 2) = lo;
    }
    for (int i = tid; i < 640; i += 512) sWo[i] = Wo[i];
    if (tid < 5) sbo[tid] = bo[tid];

    int c2 = 2 * (lane & 3), r4 = lane >> 2;
    int lr = lane & 15, lh = lane >> 4;
    int par = lane & 1;                 // 0: row r4, 1: row r4+8
    int cb  = (lane >> 1) & 1;          // cell-within-ntile
    int row32 = mt * 16 + r4 + 8 * par; // owned row (0..31)
    int cell0 = wn * 16 + cb;           // owned cells: cell0 + 2*i

    float creg[8];
    #pragma unroll
    for (int i = 0; i < 8; i++)
        creg[i] = g_c[(b0 + row32) * 128 + cell0 + 2 * i];

    // y-epilogue ownership: lanes 0-9 of each warp -> outputs w*10 + lane
    int yidx = w * 10 + lane;           // valid when lane < 10
    int yr = yidx / 5, yd = yidx - yr * 5;
    __syncthreads();

    // register double-buffer for g_pre acc-init (prefetch step 0)
    float2 pa[8], pb[8];
    {
        size_t rbase = (size_t)(b0 + mt * 16);
        #pragma unroll
        for (int i = 0; i < 8; i++) {
            int col = (wn * 8 + i) * 8 + c2;
            pa[i] = *(const float2*)(g_pre + (rbase + r4) * GATES + col);
            pb[i] = *(const float2*)(g_pre + (rbase + 8 + r4) * GATES + col);
        }
    }

    for (int tloc = 0; tloc < CHUNK; tloc++) {
        int wb = tloc & 1, rb = wb ^ 1;
        uint32_t ahb = smb + P2_H + rb * HBUF + (mt * 16 + lr) * ROWB + lh * 16;
        uint32_t alb = ahb + 8704;

        // ---- acc init from prefetched pre-gates ----
        float acc[8][4];
        #pragma unroll
        for (int i = 0; i < 8; i++) {
            acc[i][0] = pa[i].x; acc[i][1] = pa[i].y;
            acc[i][2] = pb[i].x; acc[i][3] = pb[i].y;
        }

        // ---- kp-outer GEMM: 8 independent accumulator chains per kp ----
        #pragma unroll
        for (int kp = 0; kp < 4; kp++) {
            uint32_t a0[4], a1[4], l0[4], l1[4];
            ldm_x4(a0, ahb + (2 * kp) * 32);
            ldm_x4(a1, ahb + (2 * kp + 1) * 32);
            ldm_x4(l0, alb + (2 * kp) * 32);
            ldm_x4(l1, alb + (2 * kp + 1) * 32);
            #pragma unroll
            for (int i = 0; i < 8; i++) {
                uint32_t bf[4];
                ldm_x4(bf, smb + P2_B + ((wn * 8 + i) * 8 + (lane & 7)) * ROWB
                           + (lane >> 3) * 16 + kp * 64);
                mma16816(acc[i][0], acc[i][1], acc[i][2], acc[i][3],
                         a0[0], a0[1], a0[2], a0[3], bf[0], bf[1]);
                mma16816(acc[i][0], acc[i][1], acc[i][2], acc[i][3],
                         a1[0], a1[1], a1[2], a1[3], bf[2], bf[3]);
                mma16816(acc[i][0], acc[i][1], acc[i][2], acc[i][3],
                         l0[0], l0[1], l0[2], l0[3], bf[0], bf[1]);
                mma16816(acc[i][0], acc[i][1], acc[i][2], acc[i][3],
                         l1[0], l1[1], l1[2], l1[3], bf[2], bf[3]);
            }
        }

        // ---- prefetch next step's acc-init (A-frag regs now dead) ----
        if (tloc + 1 < CHUNK) {
            size_t rbase = (size_t)(tloc + 1) * 4096 + b0 + mt * 16;
            #pragma unroll
            for (int i = 0; i < 8; i++) {
                int col = (wn * 8 + i) * 8 + c2;
                pa[i] = *(const float2*)(g_pre + (rbase + r4) * GATES + col);
                pb[i] = *(const float2*)(g_pre + (rbase + 8 + r4) * GATES + col);
            }
        }

        // ---- fragment exchange + activation (8 independent chains) ----
        char* hwh = sm + P2_H + wb * HBUF + row32 * ROWB;
        char* hwl = hwh + 8704;
        #pragma unroll
        for (int i = 0; i < 8; i++) {
            float e0 = __shfl_xor_sync(0xffffffffu, acc[i][0], 1);
            float e1 = __shfl_xor_sync(0xffffffffu, acc[i][1], 1);
            float e2 = __shfl_xor_sync(0xffffffffu, acc[i][2], 1);
            float e3 = __shfl_xor_sync(0xffffffffu, acc[i][3], 1);
            float gi = par ? e2 : acc[i][0];
            float gf = par ? e3 : acc[i][1];
            float gg = par ? acc[i][2] : e0;
            float go = par ? acc[i][3] : e1;
            float iv = sigf(gi), fv = sigf(gf);
            float gv = tanhfast(gg), ov = sigf(go);
            float cc = fmaf(fv, creg[i], iv * gv);
            creg[i] = cc;
            float hh = ov * tanhfast(cc);
            __half hhi, hlo;
            split2(hh, hhi, hlo);
            int cell = cell0 + 2 * i;
            *(__half*)(hwh + cell * 2) = hhi;
            *(__half*)(hwl + cell * 2) = hlo;
            if (tloc == CHUNK - 1) {
                g_h[(b0 + row32) * 128 + cell] = hh;
                g_c[(b0 + row32) * 128 + cell] = cc;
                if (chunk == NCH - 1) {
                    float* out_h = out + (size_t)BATCH * TDIM * 5;
                    float* out_c = out_h + (size_t)BATCH * 128;
                    out_h[(b0 + row32) * 128 + cell] = hh;
                    out_c[(b0 + row32) * 128 + cell] = cc;
                }
            }
        }
        __syncthreads();   // H(t) writes visible; all H(t-1)/y reads done

        // ---- y = h_new @ Wo^T + bo (lanes 0-9 of every warp) ----
        if (lane < 10) {
            float s0 = 0.f, s1 = 0.f;
            const char* hh_ = sm + P2_H + wb * HBUF + yr * ROWB;
            const char* hl_ = hh_ + 8704;
            const float* wrow = sWo + yd * 128;
            #pragma unroll 8
            for (int k = 0; k < 128; k += 2) {
                float2 fh = __half22float2(*(const __half2*)(hh_ + k * 2));
                float2 fl = __half22float2(*(const __half2*)(hl_ + k * 2));
                s0 = fmaf(fh.x + fl.x, wrow[k],     s0);
                s1 = fmaf(fh.y + fl.y, wrow[k + 1], s1);
            }
            int tg = chunk * CHUNK + tloc;
            out[((size_t)(b0 + yr) * TDIM + tg) * 5 + yd] = s0 + s1 + sbo[yd];
        }
    }
}

// ---------------------------------------------------------------------------
extern "C" void kernel_launch(void* const* d_in, const int* in_sizes, int n_in,
                              void* d_out, int out_size) {
    const float* xin = (const float*)d_in[0];
    const float* We  = (const float*)d_in[1];
    const float* be  = (const float*)d_in[2];
    const float* Wih = (const float*)d_in[3];
    const float* Whh = (const float*)d_in[4];
    const float* bih = (const float*)d_in[5];
    const float* bhh = (const float*)d_in[6];
    const float* Wo  = (const float*)d_in[7];
    const float* bo  = (const float*)d_in[8];
    float* out = (float*)d_out;

    cudaFuncSetAttribute(k_pre_tc, cudaFuncAttributeMaxDynamicSharedMemorySize, SMEM_P1);
    cudaFuncSetAttribute(k_recur,  cudaFuncAttributeMaxDynamicSharedMemorySize, SMEM_P2);

    k_prep<<<256, 256>>>(Wih, Whh, bih, bhh);
    k_zero<<<2048, 256>>>();
    for (int c = 0; c < NCH; c++) {
        k_pre_tc<<<dim3(128, 4), 256, SMEM_P1>>>(xin, We, be, c);
        k_recur<<<128, 512, SMEM_P2>>>(Wo, bo, out, c);
    }
}